// round 10
// baseline (speedup 1.0000x reference)
#include <cuda_runtime.h>
#include <cuda_bf16.h>
#include <cuda_fp16.h>
#include <cstdint>

// Problem constants: B=1, C=256, N=16*16*16=4096, heads=8, d=32
#define NTOK 4096
#define CCH  256
#define NHEAD 8
#define HDIM 32

// log2(e)/sqrt(32): folded into q so softmax uses ex2 directly
#define QSCALE 0.25503482617f

// ---------------- device scratch (no allocation allowed) ----------------
__device__ __align__(16) __nv_bfloat16 g_xb[CCH * NTOK];          // x bf16, [c][n]
__device__ __align__(16) __nv_bfloat16 g_Wb[4 * CCH * CCH];       // Wq|Wk|Wv|Wo bf16
__device__ __align__(16) __half g_qh[NHEAD * NTOK * HDIM];        // [h][n][d], pre-scaled
__device__ __align__(16) __half g_kh[NHEAD * NTOK * HDIM];
__device__ __align__(16) __half g_vh[NHEAD * NTOK * HDIM];
__device__ __align__(16) __nv_bfloat16 g_attnb[NTOK * CCH];       // [n][c]

// ---------------- helpers ----------------
__device__ __forceinline__ uint32_t sptr(const void* p) {
    return (uint32_t)__cvta_generic_to_shared(p);
}
__device__ __forceinline__ void ldm_x4(uint32_t& r0, uint32_t& r1, uint32_t& r2, uint32_t& r3, uint32_t addr) {
    asm volatile("ldmatrix.sync.aligned.m8n8.x4.shared.b16 {%0,%1,%2,%3}, [%4];"
                 : "=r"(r0), "=r"(r1), "=r"(r2), "=r"(r3) : "r"(addr));
}
__device__ __forceinline__ void ldm_x4t(uint32_t& r0, uint32_t& r1, uint32_t& r2, uint32_t& r3, uint32_t addr) {
    asm volatile("ldmatrix.sync.aligned.m8n8.x4.trans.shared.b16 {%0,%1,%2,%3}, [%4];"
                 : "=r"(r0), "=r"(r1), "=r"(r2), "=r"(r3) : "r"(addr));
}
__device__ __forceinline__ void mma_bf16(float* c, uint32_t a0, uint32_t a1, uint32_t a2, uint32_t a3,
                                         uint32_t b0, uint32_t b1) {
    asm volatile("mma.sync.aligned.m16n8k16.row.col.f32.bf16.bf16.f32 "
                 "{%0,%1,%2,%3}, {%4,%5,%6,%7}, {%8,%9}, {%0,%1,%2,%3};"
                 : "+f"(c[0]), "+f"(c[1]), "+f"(c[2]), "+f"(c[3])
                 : "r"(a0), "r"(a1), "r"(a2), "r"(a3), "r"(b0), "r"(b1));
}
__device__ __forceinline__ void mma_f16(float* c, uint32_t a0, uint32_t a1, uint32_t a2, uint32_t a3,
                                        uint32_t b0, uint32_t b1) {
    asm volatile("mma.sync.aligned.m16n8k16.row.col.f32.f16.f16.f32 "
                 "{%0,%1,%2,%3}, {%4,%5,%6,%7}, {%8,%9}, {%0,%1,%2,%3};"
                 : "+f"(c[0]), "+f"(c[1]), "+f"(c[2]), "+f"(c[3])
                 : "r"(a0), "r"(a1), "r"(a2), "r"(a3), "r"(b0), "r"(b1));
}
__device__ __forceinline__ uint32_t cvt_f16x2(float hi, float lo) {
    uint32_t d;
    asm volatile("cvt.rn.f16x2.f32 %0, %1, %2;" : "=r"(d) : "f"(hi), "f"(lo));
    return d;
}
__device__ __forceinline__ uint32_t ex2_h2(uint32_t v) {
    uint32_t d;
    asm volatile("ex2.approx.f16x2 %0, %1;" : "=r"(d) : "r"(v));
    return d;
}
__device__ __forceinline__ uint32_t hadd2(uint32_t a, uint32_t b) {
    uint32_t d;
    asm volatile("add.rn.f16x2 %0, %1, %2;" : "=r"(d) : "r"(a), "r"(b));
    return d;
}
__device__ __forceinline__ float2 unpack_h2(uint32_t v) {
    float2 r;
    asm("{\n\t.reg .b16 lo,hi;\n\tmov.b32 {lo,hi}, %2;\n\tcvt.f32.f16 %0, lo;\n\tcvt.f32.f16 %1, hi;\n\t}"
        : "=f"(r.x), "=f"(r.y) : "r"(v));
    return r;
}
__device__ __forceinline__ void cp16(uint32_t dst, const void* src) {
    asm volatile("cp.async.cg.shared.global [%0], [%1], 16;" :: "r"(dst), "l"(src));
}
__device__ __forceinline__ void cp_commit() {
    asm volatile("cp.async.commit_group;");
}
template <int N>
__device__ __forceinline__ void cp_wait() {
    asm volatile("cp.async.wait_group %0;" :: "n"(N));
}

// ---------------------------------------------------------------------------
// Convert x + 4 weight matrices fp32 -> bf16. Grid-stride, 4 float4/thread.
// ---------------------------------------------------------------------------
__global__ void __launch_bounds__(256) convert_kernel(
    const float* __restrict__ x,
    const float* __restrict__ Wq, const float* __restrict__ Wk,
    const float* __restrict__ Wv, const float* __restrict__ Wo)
{
    #pragma unroll
    for (int t = 0; t < 4; t++) {
        int i4 = (blockIdx.x * 256 + threadIdx.x) + t * 81920;
        const float* src;
        __nv_bfloat16* dst;
        int off4;
        if (i4 < 262144) { src = x; dst = g_xb; off4 = i4; }
        else {
            int j = i4 - 262144;
            int r = j >> 14;
            off4 = j & 16383;
            src = (r == 0) ? Wq : (r == 1) ? Wk : (r == 2) ? Wv : Wo;
            dst = g_Wb + r * (CCH * CCH);
        }
        float4 v = ((const float4*)src)[off4];
        __nv_bfloat162 lo = __floats2bfloat162_rn(v.x, v.y);
        __nv_bfloat162 hi = __floats2bfloat162_rn(v.z, v.w);
        uint2 pk;
        pk.x = *(uint32_t*)&lo;
        pk.y = *(uint32_t*)&hi;
        *(uint2*)&dst[off4 * 4] = pk;
    }
}

// ---------------------------------------------------------------------------
// QKV projection, bf16 mma, 64(m) x 128(n) tiles -> grid (32,4,3)=384 CTAs.
// 3-stage cp.async. 8 warps = 2(m) x 4(n), warp tile 32x32. (R9 shape, kept)
// ---------------------------------------------------------------------------
__global__ void __launch_bounds__(256, 2) gemm_qkv_kernel(
    const float* __restrict__ bq, const float* __restrict__ bk, const float* __restrict__ bv)
{
    const __nv_bfloat16* W; const float* bias; __half* outp; float sc;
    if (blockIdx.z == 0)      { W = g_Wb;                 bias = bq; outp = g_qh; sc = QSCALE; }
    else if (blockIdx.z == 1) { W = g_Wb + CCH * CCH;     bias = bk; outp = g_kh; sc = 1.0f; }
    else                      { W = g_Wb + 2 * CCH * CCH; bias = bv; outp = g_vh; sc = 1.0f; }

    __shared__ __nv_bfloat16 As[3][64 * 40];
    __shared__ __nv_bfloat16 Bs[3][32 * 136];

    const int tid  = threadIdx.x;
    const int lane = tid & 31;
    const int wid  = tid >> 5;
    const int wm   = wid & 1;
    const int wn   = wid >> 1;
    const int o0   = blockIdx.y * 64;
    const int n0   = blockIdx.x * 128;

    const int arow = tid >> 2, ac4 = tid & 3;
    const int brow = tid >> 4, bc4 = tid & 15;

    auto issue = [&](int s, int b) {
        const char* wsrc = (const char*)W + (size_t)(o0 + arow) * CCH * 2 + s * 64 + ac4 * 16;
        cp16(sptr(&As[b][arow * 40]) + ac4 * 16, wsrc);
        const char* xsrc = (const char*)g_xb + (size_t)(s * 32 + brow) * NTOK * 2 + (size_t)n0 * 2 + bc4 * 16;
        cp16(sptr(&Bs[b][brow * 136]) + bc4 * 16, xsrc);
        cp16(sptr(&Bs[b][(brow + 16) * 136]) + bc4 * 16, xsrc + (size_t)16 * NTOK * 2);
        cp_commit();
    };
    issue(0, 0);
    issue(1, 1);

    float acc[2][4][4];
    #pragma unroll
    for (int i = 0; i < 2; i++)
        #pragma unroll
        for (int j = 0; j < 4; j++)
            #pragma unroll
            for (int r = 0; r < 4; r++) acc[i][j][r] = 0.0f;

    int cur = 0;
    for (int s = 0; s < 8; s++) {
        if (s == 7) cp_wait<0>(); else cp_wait<1>();
        __syncthreads();
        if (s + 2 < 8) {
            int nb = cur + 2; if (nb >= 3) nb -= 3;
            issue(s + 2, nb);
        }
        const uint32_t asb = sptr(As[cur]);
        const uint32_t bsb = sptr(Bs[cur]);
        cur++; if (cur == 3) cur = 0;

        #pragma unroll
        for (int ks = 0; ks < 2; ks++) {
            uint32_t a[2][4];
            #pragma unroll
            for (int mi = 0; mi < 2; mi++) {
                int row = wm * 32 + mi * 16 + (lane & 15);
                int col = (lane >> 4) * 8 + ks * 16;
                ldm_x4(a[mi][0], a[mi][1], a[mi][2], a[mi][3], asb + (uint32_t)(row * 40 + col) * 2);
            }
            uint32_t b[2][4];
            #pragma unroll
            for (int nq = 0; nq < 2; nq++) {
                int krow = ks * 16 + (lane & 7) + ((lane & 8) ? 8 : 0);
                int ncol = wn * 32 + nq * 16 + ((lane & 16) ? 8 : 0);
                ldm_x4t(b[nq][0], b[nq][1], b[nq][2], b[nq][3], bsb + (uint32_t)(krow * 136 + ncol) * 2);
            }
            #pragma unroll
            for (int mi = 0; mi < 2; mi++)
                #pragma unroll
                for (int nj = 0; nj < 4; nj++) {
                    int nq = nj >> 1, sel = nj & 1;
                    mma_bf16(acc[mi][nj], a[mi][0], a[mi][1], a[mi][2], a[mi][3],
                             b[nq][2 * sel], b[nq][2 * sel + 1]);
                }
        }
    }

    float bz[2][2];
    #pragma unroll
    for (int mi = 0; mi < 2; mi++)
        #pragma unroll
        for (int hh = 0; hh < 2; hh++)
            bz[mi][hh] = bias[o0 + wm * 32 + mi * 16 + (lane >> 2) + 8 * hh];

    #pragma unroll
    for (int mi = 0; mi < 2; mi++)
        #pragma unroll
        for (int nj = 0; nj < 4; nj++)
            #pragma unroll
            for (int r = 0; r < 4; r++) {
                int m = o0 + wm * 32 + mi * 16 + (lane >> 2) + (r >> 1) * 8;
                int n = n0 + wn * 32 + nj * 8 + 2 * (lane & 3) + (r & 1);
                float v = (acc[mi][nj][r] + bz[mi][r >> 1]) * sc;
                outp[((m >> 5) << 17) + n * HDIM + (m & 31)] = __float2half(v);
            }
}

// ---------------------------------------------------------------------------
// Flash attention, fp16 mma, ex2.f16x2 softmax, cp.async 3-stage.
// NEW SHAPE: 128 threads / 4 warps per CTA; each warp covers 32 query rows
// (two m16 tiles). K/V fragments loaded ONCE per chunk and reused across the
// two m-tiles -> per-query LDSM duplication halves (4 warps replicate K/V
// instead of 8). 4 CTAs/SM resident. Same numerics as R8.
// ---------------------------------------------------------------------------
#define TQ 128
#define TK 64
#define PADS 40

__global__ void __launch_bounds__(128, 4) attn_mma_kernel()
{
    const int h    = blockIdx.y;
    const int q0   = blockIdx.x * TQ;
    const int tid  = threadIdx.x;   // 0..127
    const int wid  = tid >> 5;      // 0..3
    const int lane = tid & 31;

    const __half* __restrict__ qh = g_qh + (h << 17);
    const __half* __restrict__ kh = g_kh + (h << 17);
    const __half* __restrict__ vh = g_vh + (h << 17);

    __shared__ __half Qs[TQ * PADS];
    __shared__ __half Ks[3][TK * PADS];
    __shared__ __half Vs[3][TK * PADS];

    const int prow = tid >> 2, pch = tid & 3;   // prow 0..31; rows prow, prow+32

    auto issue = [&](int kt, int b) {
        #pragma unroll
        for (int r = 0; r < 2; r++) {
            int row = prow + r * 32;
            const char* ksrc = (const char*)kh + (size_t)kt * TK * HDIM * 2 + row * 64 + pch * 16;
            const char* vsrc = (const char*)vh + (size_t)kt * TK * HDIM * 2 + row * 64 + pch * 16;
            cp16(sptr(&Ks[b][row * PADS]) + pch * 16, ksrc);
            cp16(sptr(&Vs[b][row * PADS]) + pch * 16, vsrc);
        }
        cp_commit();
    };
    issue(0, 0);
    issue(1, 1);

    // load Q tile (128 x 32 fp16 = 512 uint4; 128 threads x 4)
    {
        const uint4* qsrc = (const uint4*)(qh + q0 * HDIM);
        #pragma unroll
        for (int t = 0; t < 4; t++) {
            int idx = tid + t * 128;
            int row = idx >> 2, ch = idx & 3;
            *(uint4*)((char*)Qs + row * (PADS * 2) + ch * 16) = qsrc[idx];
        }
    }
    __syncthreads();

    // Q fragments: [mi][ks][4]  (two m16 tiles per warp)
    uint32_t qa[2][2][4];
    {
        const uint32_t qbase = sptr(Qs);
        #pragma unroll
        for (int mi = 0; mi < 2; mi++)
            #pragma unroll
            for (int ks = 0; ks < 2; ks++) {
                int row = wid * 32 + mi * 16 + (lane & 15);
                int col = (lane >> 4) * 8 + ks * 16;
                ldm_x4(qa[mi][ks][0], qa[mi][ks][1], qa[mi][ks][2], qa[mi][ks][3],
                       qbase + (uint32_t)(row * PADS + col) * 2);
            }
    }

    float o_[2][4][4];   // [mi][dt][4]
    #pragma unroll
    for (int mi = 0; mi < 2; mi++)
        #pragma unroll
        for (int i = 0; i < 4; i++)
            #pragma unroll
            for (int j = 0; j < 4; j++) o_[mi][i][j] = 0.0f;
    float l0[2] = {0.0f, 0.0f}, l1[2] = {0.0f, 0.0f};

    const uint32_t k_lane_off = (uint32_t)((lane & 7) * PADS + (lane >> 3) * 8) * 2;
    const uint32_t v_lane_row = (lane & 7) + ((lane & 8) ? 8 : 0);
    const uint32_t v_lane_col = (lane & 16) ? 8 : 0;

    int cur = 0;
    for (int kt = 0; kt < NTOK / TK; kt++) {
        if (kt == NTOK / TK - 1) cp_wait<0>(); else cp_wait<1>();
        __syncthreads();
        if (kt + 2 < NTOK / TK) {
            int nb = cur + 2; if (nb >= 3) nb -= 3;
            issue(kt + 2, nb);
        }
        const uint32_t ksb = sptr(Ks[cur]);
        const uint32_t vsb = sptr(Vs[cur]);
        cur++; if (cur == 3) cur = 0;

        uint32_t lh0[2] = {0, 0}, lh1[2] = {0, 0};

        #pragma unroll
        for (int c = 0; c < 4; c++) {
            // K fragments for this 16-key chunk: loaded ONCE, reused by both m-tiles
            uint32_t ka0, ka1, ka2, ka3, kb0, kb1, kb2, kb3;
            ldm_x4(ka0, ka1, ka2, ka3, ksb + (uint32_t)((16 * c) * PADS) * 2 + k_lane_off);
            ldm_x4(kb0, kb1, kb2, kb3, ksb + (uint32_t)((16 * c + 8) * PADS) * 2 + k_lane_off);

            // V fragments: loaded ONCE, reused by both m-tiles
            uint32_t vb[8];
            {
                uint32_t addrA = vsb + (uint32_t)((16 * c + v_lane_row) * PADS + v_lane_col) * 2;
                ldm_x4t(vb[0], vb[1], vb[2], vb[3], addrA);
                ldm_x4t(vb[4], vb[5], vb[6], vb[7], addrA + 32);
            }

            #pragma unroll
            for (int mi = 0; mi < 2; mi++) {
                float s0[4], s1[4];
                s0[0] = s0[1] = s0[2] = s0[3] = 0.0f;
                s1[0] = s1[1] = s1[2] = s1[3] = 0.0f;
                mma_f16(s0, qa[mi][0][0], qa[mi][0][1], qa[mi][0][2], qa[mi][0][3], ka0, ka1);
                mma_f16(s0, qa[mi][1][0], qa[mi][1][1], qa[mi][1][2], qa[mi][1][3], ka2, ka3);
                mma_f16(s1, qa[mi][0][0], qa[mi][0][1], qa[mi][0][2], qa[mi][0][3], kb0, kb1);
                mma_f16(s1, qa[mi][1][0], qa[mi][1][1], qa[mi][1][2], qa[mi][1][3], kb2, kb3);

                uint32_t a0 = ex2_h2(cvt_f16x2(s0[1], s0[0]));
                uint32_t a1 = ex2_h2(cvt_f16x2(s0[3], s0[2]));
                uint32_t a2 = ex2_h2(cvt_f16x2(s1[1], s1[0]));
                uint32_t a3 = ex2_h2(cvt_f16x2(s1[3], s1[2]));

                lh0[mi] = hadd2(lh0[mi], a0);
                lh0[mi] = hadd2(lh0[mi], a2);
                lh1[mi] = hadd2(lh1[mi], a1);
                lh1[mi] = hadd2(lh1[mi], a3);

                #pragma unroll
                for (int dt = 0; dt < 4; dt++)
                    mma_f16(o_[mi][dt], a0, a1, a2, a3, vb[2 * dt], vb[2 * dt + 1]);
            }
        }

        #pragma unroll
        for (int mi = 0; mi < 2; mi++) {
            float2 f0 = unpack_h2(lh0[mi]);
            float2 f1 = unpack_h2(lh1[mi]);
            l0[mi] += f0.x + f0.y;
            l1[mi] += f1.x + f1.y;
        }
    }

    // finalize
    #pragma unroll
    for (int mi = 0; mi < 2; mi++) {
        l0[mi] += __shfl_xor_sync(0xffffffffu, l0[mi], 1);
        l0[mi] += __shfl_xor_sync(0xffffffffu, l0[mi], 2);
        l1[mi] += __shfl_xor_sync(0xffffffffu, l1[mi], 1);
        l1[mi] += __shfl_xor_sync(0xffffffffu, l1[mi], 2);
        const float inv0 = 1.0f / l0[mi];
        const float inv1 = 1.0f / l1[mi];

        const int r0 = q0 + wid * 32 + mi * 16 + (lane >> 2);
        const int r1 = r0 + 8;
        const int cbase = h * 32 + 2 * (lane & 3);
        #pragma unroll
        for (int dt = 0; dt < 4; dt++) {
            int c = cbase + dt * 8;
            __nv_bfloat162 v0 = __floats2bfloat162_rn(o_[mi][dt][0] * inv0, o_[mi][dt][1] * inv0);
            __nv_bfloat162 v1 = __floats2bfloat162_rn(o_[mi][dt][2] * inv1, o_[mi][dt][3] * inv1);
            *(uint32_t*)&g_attnb[r0 * CCH + c] = *(uint32_t*)&v0;
            *(uint32_t*)&g_attnb[r1 * CCH + c] = *(uint32_t*)&v1;
        }
    }
}

// ---------------------------------------------------------------------------
// O projection + residual, bf16 mma, 64(m) x 128(n) tiles -> 128 CTAs.
// (Reverted to the R5/R8 measured-best shape.)
// ---------------------------------------------------------------------------
__global__ void __launch_bounds__(256, 2) gemm_o_kernel(
    const float* __restrict__ x,
    const float* __restrict__ bo, const float* __restrict__ gamma,
    float* __restrict__ out)
{
    const __nv_bfloat16* W = g_Wb + 3 * CCH * CCH;

    __shared__ __nv_bfloat16 As[3][64 * 40];    // [m][k]
    __shared__ __nv_bfloat16 Bs[3][128 * 40];   // [n][k]

    const int tid  = threadIdx.x;
    const int lane = tid & 31;
    const int wid  = tid >> 5;
    const int wm   = wid & 1;
    const int wn   = wid >> 1;
    const int o0   = blockIdx.y * 64;
    const int n0   = blockIdx.x * 128;

    const int arow = tid >> 2, ac4 = tid & 3;

    auto issue = [&](int s, int b) {
        const char* wsrc = (const char*)W + (size_t)(o0 + arow) * CCH * 2 + s * 64 + ac4 * 16;
        cp16(sptr(&As[b][arow * 40]) + ac4 * 16, wsrc);
        const char* bsrc = (const char*)g_attnb + (size_t)(n0 + arow) * CCH * 2 + s * 64 + ac4 * 16;
        cp16(sptr(&Bs[b][arow * 40]) + ac4 * 16, bsrc);
        cp16(sptr(&Bs[b][(arow + 64) * 40]) + ac4 * 16, bsrc + (size_t)64 * CCH * 2);
        cp_commit();
    };
    issue(0, 0);
    issue(1, 1);

    float acc[2][4][4];
    #pragma unroll
    for (int i = 0; i < 2; i++)
        #pragma unroll
        for (int j = 0; j < 4; j++)
            #pragma unroll
            for (int r = 0; r < 4; r++) acc[i][j][r] = 0.0f;

    int cur = 0;
    for (int s = 0; s < 8; s++) {
        if (s == 7) cp_wait<0>(); else cp_wait<1>();
        __syncthreads();
        if (s + 2 < 8) {
            int nb = cur + 2; if (nb >= 3) nb -= 3;
            issue(s + 2, nb);
        }
        const uint32_t asb = sptr(As[cur]);
        const uint32_t bsb = sptr(Bs[cur]);
        cur++; if (cur == 3) cur = 0;

        uint32_t b[4][4];
        #pragma unroll
        for (int nt = 0; nt < 4; nt++) {
            uint32_t addr = bsb + (uint32_t)((wn * 32 + nt * 8 + (lane & 7)) * 40 + (lane >> 3) * 8) * 2;
            ldm_x4(b[nt][0], b[nt][1], b[nt][2], b[nt][3], addr);
        }
        #pragma unroll
        for (int ks = 0; ks < 2; ks++) {
            uint32_t a[2][4];
            #pragma unroll
            for (int mi = 0; mi < 2; mi++) {
                int row = wm * 32 + mi * 16 + (lane & 15);
                int col = (lane >> 4) * 8 + ks * 16;
                ldm_x4(a[mi][0], a[mi][1], a[mi][2], a[mi][3], asb + (uint32_t)(row * 40 + col) * 2);
            }
            #pragma unroll
            for (int mi = 0; mi < 2; mi++)
                #pragma unroll
                for (int nt = 0; nt < 4; nt++)
                    mma_bf16(acc[mi][nt], a[mi][0], a[mi][1], a[mi][2], a[mi][3],
                             b[nt][2 * ks], b[nt][2 * ks + 1]);
        }
    }

    const float g = gamma[0];
    float bz[2][2];
    #pragma unroll
    for (int mi = 0; mi < 2; mi++)
        #pragma unroll
        for (int hh = 0; hh < 2; hh++)
            bz[mi][hh] = bo[o0 + wm * 32 + mi * 16 + (lane >> 2) + 8 * hh];

    #pragma unroll
    for (int mi = 0; mi < 2; mi++)
        #pragma unroll
        for (int nt = 0; nt < 4; nt++) {
            int m = o0 + wm * 32 + mi * 16 + (lane >> 2);
            int n = n0 + wn * 32 + nt * 8 + 2 * (lane & 3);
            {
                float2 xv = *(const float2*)&x[m * NTOK + n];
                float2 ov;
                ov.x = xv.x + g * (acc[mi][nt][0] + bz[mi][0]);
                ov.y = xv.y + g * (acc[mi][nt][1] + bz[mi][0]);
                *(float2*)&out[m * NTOK + n] = ov;
            }
            {
                int m2 = m + 8;
                float2 xv = *(const float2*)&x[m2 * NTOK + n];
                float2 ov;
                ov.x = xv.x + g * (acc[mi][nt][2] + bz[mi][1]);
                ov.y = xv.y + g * (acc[mi][nt][3] + bz[mi][1]);
                *(float2*)&out[m2 * NTOK + n] = ov;
            }
        }
}

// ---------------------------------------------------------------------------
// Launch: inputs x, Wq, bq, Wk, bk, Wv, bv, Wo, bo, gamma
// ---------------------------------------------------------------------------
extern "C" void kernel_launch(void* const* d_in, const int* in_sizes, int n_in,
                              void* d_out, int out_size)
{
    const float* x     = (const float*)d_in[0];
    const float* Wq    = (const float*)d_in[1];
    const float* bq    = (const float*)d_in[2];
    const float* Wk    = (const float*)d_in[3];
    const float* bk    = (const float*)d_in[4];
    const float* Wv    = (const float*)d_in[5];
    const float* bv    = (const float*)d_in[6];
    const float* Wo    = (const float*)d_in[7];
    const float* bo    = (const float*)d_in[8];
    const float* gamma = (const float*)d_in[9];
    float* out = (float*)d_out;

    convert_kernel<<<320, 256>>>(x, Wq, Wk, Wv, Wo);

    dim3 qkvGrid(NTOK / 128, CCH / 64, 3);
    gemm_qkv_kernel<<<qkvGrid, 256>>>(bq, bk, bv);

    dim3 attnGrid(NTOK / TQ, NHEAD, 1);
    attn_mma_kernel<<<attnGrid, 128>>>();

    dim3 oGrid(NTOK / 128, CCH / 64, 1);
    gemm_o_kernel<<<oGrid, 256>>>(x, bo, gamma, out);
}

// round 12
// speedup vs baseline: 1.1231x; 1.1231x over previous
#include <cuda_runtime.h>
#include <cuda_bf16.h>
#include <cuda_fp16.h>
#include <cstdint>

// Problem constants: B=1, C=256, N=16*16*16=4096, heads=8, d=32
#define NTOK 4096
#define CCH  256
#define NHEAD 8
#define HDIM 32

// log2(e)/sqrt(32): folded into q so softmax uses ex2 directly
#define QSCALE 0.25503482617f

// ---------------- device scratch (no allocation allowed) ----------------
__device__ __align__(16) __nv_bfloat16 g_xb[CCH * NTOK];          // x bf16, [c][n]
__device__ __align__(16) __nv_bfloat16 g_Wb[4 * CCH * CCH];       // Wq|Wk|Wv|Wo bf16
__device__ __align__(16) __half g_qh[NHEAD * NTOK * HDIM];        // [h][n][d], pre-scaled
__device__ __align__(16) __half g_kh[NHEAD * NTOK * HDIM];
__device__ __align__(16) __half g_vh[NHEAD * NTOK * HDIM];
__device__ __align__(16) __nv_bfloat16 g_attnb[NTOK * CCH];       // [n][c]

// ---------------- helpers ----------------
__device__ __forceinline__ uint32_t sptr(const void* p) {
    return (uint32_t)__cvta_generic_to_shared(p);
}
__device__ __forceinline__ void ldm_x4(uint32_t& r0, uint32_t& r1, uint32_t& r2, uint32_t& r3, uint32_t addr) {
    asm volatile("ldmatrix.sync.aligned.m8n8.x4.shared.b16 {%0,%1,%2,%3}, [%4];"
                 : "=r"(r0), "=r"(r1), "=r"(r2), "=r"(r3) : "r"(addr));
}
__device__ __forceinline__ void ldm_x4t(uint32_t& r0, uint32_t& r1, uint32_t& r2, uint32_t& r3, uint32_t addr) {
    asm volatile("ldmatrix.sync.aligned.m8n8.x4.trans.shared.b16 {%0,%1,%2,%3}, [%4];"
                 : "=r"(r0), "=r"(r1), "=r"(r2), "=r"(r3) : "r"(addr));
}
__device__ __forceinline__ void mma_bf16(float* c, uint32_t a0, uint32_t a1, uint32_t a2, uint32_t a3,
                                         uint32_t b0, uint32_t b1) {
    asm volatile("mma.sync.aligned.m16n8k16.row.col.f32.bf16.bf16.f32 "
                 "{%0,%1,%2,%3}, {%4,%5,%6,%7}, {%8,%9}, {%0,%1,%2,%3};"
                 : "+f"(c[0]), "+f"(c[1]), "+f"(c[2]), "+f"(c[3])
                 : "r"(a0), "r"(a1), "r"(a2), "r"(a3), "r"(b0), "r"(b1));
}
__device__ __forceinline__ void mma_f16(float* c, uint32_t a0, uint32_t a1, uint32_t a2, uint32_t a3,
                                        uint32_t b0, uint32_t b1) {
    asm volatile("mma.sync.aligned.m16n8k16.row.col.f32.f16.f16.f32 "
                 "{%0,%1,%2,%3}, {%4,%5,%6,%7}, {%8,%9}, {%0,%1,%2,%3};"
                 : "+f"(c[0]), "+f"(c[1]), "+f"(c[2]), "+f"(c[3])
                 : "r"(a0), "r"(a1), "r"(a2), "r"(a3), "r"(b0), "r"(b1));
}
__device__ __forceinline__ uint32_t cvt_f16x2(float hi, float lo) {
    uint32_t d;
    asm volatile("cvt.rn.f16x2.f32 %0, %1, %2;" : "=r"(d) : "f"(hi), "f"(lo));
    return d;
}
__device__ __forceinline__ uint32_t ex2_h2(uint32_t v) {
    uint32_t d;
    asm volatile("ex2.approx.f16x2 %0, %1;" : "=r"(d) : "r"(v));
    return d;
}
__device__ __forceinline__ uint32_t hadd2(uint32_t a, uint32_t b) {
    uint32_t d;
    asm volatile("add.rn.f16x2 %0, %1, %2;" : "=r"(d) : "r"(a), "r"(b));
    return d;
}
__device__ __forceinline__ float2 unpack_h2(uint32_t v) {
    float2 r;
    asm("{\n\t.reg .b16 lo,hi;\n\tmov.b32 {lo,hi}, %2;\n\tcvt.f32.f16 %0, lo;\n\tcvt.f32.f16 %1, hi;\n\t}"
        : "=f"(r.x), "=f"(r.y) : "r"(v));
    return r;
}
__device__ __forceinline__ void cp16(uint32_t dst, const void* src) {
    asm volatile("cp.async.cg.shared.global [%0], [%1], 16;" :: "r"(dst), "l"(src));
}
__device__ __forceinline__ void cp_commit() {
    asm volatile("cp.async.commit_group;");
}
template <int N>
__device__ __forceinline__ void cp_wait() {
    asm volatile("cp.async.wait_group %0;" :: "n"(N));
}

// ---------------------------------------------------------------------------
// Convert x + 4 weight matrices fp32 -> bf16. Grid-stride, 4 float4/thread.
// ---------------------------------------------------------------------------
__global__ void __launch_bounds__(256) convert_kernel(
    const float* __restrict__ x,
    const float* __restrict__ Wq, const float* __restrict__ Wk,
    const float* __restrict__ Wv, const float* __restrict__ Wo)
{
    #pragma unroll
    for (int t = 0; t < 4; t++) {
        int i4 = (blockIdx.x * 256 + threadIdx.x) + t * 81920;
        const float* src;
        __nv_bfloat16* dst;
        int off4;
        if (i4 < 262144) { src = x; dst = g_xb; off4 = i4; }
        else {
            int j = i4 - 262144;
            int r = j >> 14;
            off4 = j & 16383;
            src = (r == 0) ? Wq : (r == 1) ? Wk : (r == 2) ? Wv : Wo;
            dst = g_Wb + r * (CCH * CCH);
        }
        float4 v = ((const float4*)src)[off4];
        __nv_bfloat162 lo = __floats2bfloat162_rn(v.x, v.y);
        __nv_bfloat162 hi = __floats2bfloat162_rn(v.z, v.w);
        uint2 pk;
        pk.x = *(uint32_t*)&lo;
        pk.y = *(uint32_t*)&hi;
        *(uint2*)&dst[off4 * 4] = pk;
    }
}

// ---------------------------------------------------------------------------
// QKV projection, bf16 mma, 64(m) x 128(n) tiles -> grid (32,4,3)=384 CTAs.
// 3-stage cp.async. 8 warps = 2(m) x 4(n), warp tile 32x32. (R9 shape)
// ---------------------------------------------------------------------------
__global__ void __launch_bounds__(256, 2) gemm_qkv_kernel(
    const float* __restrict__ bq, const float* __restrict__ bk, const float* __restrict__ bv)
{
    const __nv_bfloat16* W; const float* bias; __half* outp; float sc;
    if (blockIdx.z == 0)      { W = g_Wb;                 bias = bq; outp = g_qh; sc = QSCALE; }
    else if (blockIdx.z == 1) { W = g_Wb + CCH * CCH;     bias = bk; outp = g_kh; sc = 1.0f; }
    else                      { W = g_Wb + 2 * CCH * CCH; bias = bv; outp = g_vh; sc = 1.0f; }

    __shared__ __nv_bfloat16 As[3][64 * 40];
    __shared__ __nv_bfloat16 Bs[3][32 * 136];

    const int tid  = threadIdx.x;
    const int lane = tid & 31;
    const int wid  = tid >> 5;
    const int wm   = wid & 1;
    const int wn   = wid >> 1;
    const int o0   = blockIdx.y * 64;
    const int n0   = blockIdx.x * 128;

    const int arow = tid >> 2, ac4 = tid & 3;
    const int brow = tid >> 4, bc4 = tid & 15;

    auto issue = [&](int s, int b) {
        const char* wsrc = (const char*)W + (size_t)(o0 + arow) * CCH * 2 + s * 64 + ac4 * 16;
        cp16(sptr(&As[b][arow * 40]) + ac4 * 16, wsrc);
        const char* xsrc = (const char*)g_xb + (size_t)(s * 32 + brow) * NTOK * 2 + (size_t)n0 * 2 + bc4 * 16;
        cp16(sptr(&Bs[b][brow * 136]) + bc4 * 16, xsrc);
        cp16(sptr(&Bs[b][(brow + 16) * 136]) + bc4 * 16, xsrc + (size_t)16 * NTOK * 2);
        cp_commit();
    };
    issue(0, 0);
    issue(1, 1);

    float acc[2][4][4];
    #pragma unroll
    for (int i = 0; i < 2; i++)
        #pragma unroll
        for (int j = 0; j < 4; j++)
            #pragma unroll
            for (int r = 0; r < 4; r++) acc[i][j][r] = 0.0f;

    int cur = 0;
    for (int s = 0; s < 8; s++) {
        if (s == 7) cp_wait<0>(); else cp_wait<1>();
        __syncthreads();
        if (s + 2 < 8) {
            int nb = cur + 2; if (nb >= 3) nb -= 3;
            issue(s + 2, nb);
        }
        const uint32_t asb = sptr(As[cur]);
        const uint32_t bsb = sptr(Bs[cur]);
        cur++; if (cur == 3) cur = 0;

        #pragma unroll
        for (int ks = 0; ks < 2; ks++) {
            uint32_t a[2][4];
            #pragma unroll
            for (int mi = 0; mi < 2; mi++) {
                int row = wm * 32 + mi * 16 + (lane & 15);
                int col = (lane >> 4) * 8 + ks * 16;
                ldm_x4(a[mi][0], a[mi][1], a[mi][2], a[mi][3], asb + (uint32_t)(row * 40 + col) * 2);
            }
            uint32_t b[2][4];
            #pragma unroll
            for (int nq = 0; nq < 2; nq++) {
                int krow = ks * 16 + (lane & 7) + ((lane & 8) ? 8 : 0);
                int ncol = wn * 32 + nq * 16 + ((lane & 16) ? 8 : 0);
                ldm_x4t(b[nq][0], b[nq][1], b[nq][2], b[nq][3], bsb + (uint32_t)(krow * 136 + ncol) * 2);
            }
            #pragma unroll
            for (int mi = 0; mi < 2; mi++)
                #pragma unroll
                for (int nj = 0; nj < 4; nj++) {
                    int nq = nj >> 1, sel = nj & 1;
                    mma_bf16(acc[mi][nj], a[mi][0], a[mi][1], a[mi][2], a[mi][3],
                             b[nq][2 * sel], b[nq][2 * sel + 1]);
                }
        }
    }

    float bz[2][2];
    #pragma unroll
    for (int mi = 0; mi < 2; mi++)
        #pragma unroll
        for (int hh = 0; hh < 2; hh++)
            bz[mi][hh] = bias[o0 + wm * 32 + mi * 16 + (lane >> 2) + 8 * hh];

    #pragma unroll
    for (int mi = 0; mi < 2; mi++)
        #pragma unroll
        for (int nj = 0; nj < 4; nj++)
            #pragma unroll
            for (int r = 0; r < 4; r++) {
                int m = o0 + wm * 32 + mi * 16 + (lane >> 2) + (r >> 1) * 8;
                int n = n0 + wn * 32 + nj * 8 + 2 * (lane & 3) + (r & 1);
                float v = (acc[mi][nj][r] + bz[mi][r >> 1]) * sc;
                outp[((m >> 5) << 17) + n * HDIM + (m & 31)] = __float2half(v);
            }
}

// ---------------------------------------------------------------------------
// Flash attention, fp16 mma, ex2.approx.f16x2 softmax. EXACT R8 shape
// (measured best): 256 threads, 8 warps x 16 query rows, cp.async 3-stage.
// ---------------------------------------------------------------------------
#define TQ 128
#define TK 64
#define PADS 40

__global__ void __launch_bounds__(256, 2) attn_mma_kernel()
{
    const int h    = blockIdx.y;
    const int q0   = blockIdx.x * TQ;
    const int tid  = threadIdx.x;
    const int wid  = tid >> 5;
    const int lane = tid & 31;

    const __half* __restrict__ qh = g_qh + (h << 17);
    const __half* __restrict__ kh = g_kh + (h << 17);
    const __half* __restrict__ vh = g_vh + (h << 17);

    __shared__ __half Qs[TQ * PADS];
    __shared__ __half Ks[3][TK * PADS];
    __shared__ __half Vs[3][TK * PADS];

    const int prow = tid >> 2, pch = tid & 3;

    auto issue = [&](int kt, int b) {
        const char* ksrc = (const char*)kh + (size_t)kt * TK * HDIM * 2 + prow * 64 + pch * 16;
        const char* vsrc = (const char*)vh + (size_t)kt * TK * HDIM * 2 + prow * 64 + pch * 16;
        cp16(sptr(&Ks[b][prow * PADS]) + pch * 16, ksrc);
        cp16(sptr(&Vs[b][prow * PADS]) + pch * 16, vsrc);
        cp_commit();
    };
    issue(0, 0);
    issue(1, 1);

    {
        const uint4* qsrc = (const uint4*)(qh + q0 * HDIM);
        #pragma unroll
        for (int t = 0; t < 2; t++) {
            int idx = tid + t * 256;
            int row = idx >> 2, ch = idx & 3;
            *(uint4*)((char*)Qs + row * (PADS * 2) + ch * 16) = qsrc[idx];
        }
    }
    __syncthreads();

    uint32_t qa[2][4];
    {
        const uint32_t qbase = sptr(Qs);
        #pragma unroll
        for (int ks = 0; ks < 2; ks++) {
            int row = wid * 16 + (lane & 15);
            int col = (lane >> 4) * 8 + ks * 16;
            ldm_x4(qa[ks][0], qa[ks][1], qa[ks][2], qa[ks][3],
                   qbase + (uint32_t)(row * PADS + col) * 2);
        }
    }

    float o_[4][4];
    #pragma unroll
    for (int i = 0; i < 4; i++)
        #pragma unroll
        for (int j = 0; j < 4; j++) o_[i][j] = 0.0f;
    float l0 = 0.0f, l1 = 0.0f;

    const uint32_t k_lane_off = (uint32_t)((lane & 7) * PADS + (lane >> 3) * 8) * 2;
    const uint32_t v_lane_row = (lane & 7) + ((lane & 8) ? 8 : 0);
    const uint32_t v_lane_col = (lane & 16) ? 8 : 0;

    int cur = 0;
    for (int kt = 0; kt < NTOK / TK; kt++) {
        if (kt == NTOK / TK - 1) cp_wait<0>(); else cp_wait<1>();
        __syncthreads();
        if (kt + 2 < NTOK / TK) {
            int nb = cur + 2; if (nb >= 3) nb -= 3;
            issue(kt + 2, nb);
        }
        const uint32_t ksb = sptr(Ks[cur]);
        const uint32_t vsb = sptr(Vs[cur]);
        cur++; if (cur == 3) cur = 0;

        uint32_t lh0 = 0, lh1 = 0;

        #pragma unroll
        for (int c = 0; c < 4; c++) {
            float s0[4], s1[4];
            s0[0] = s0[1] = s0[2] = s0[3] = 0.0f;
            s1[0] = s1[1] = s1[2] = s1[3] = 0.0f;
            {
                uint32_t k0, k1, k2, k3;
                ldm_x4(k0, k1, k2, k3, ksb + (uint32_t)((16 * c) * PADS) * 2 + k_lane_off);
                mma_f16(s0, qa[0][0], qa[0][1], qa[0][2], qa[0][3], k0, k1);
                mma_f16(s0, qa[1][0], qa[1][1], qa[1][2], qa[1][3], k2, k3);
            }
            {
                uint32_t k0, k1, k2, k3;
                ldm_x4(k0, k1, k2, k3, ksb + (uint32_t)((16 * c + 8) * PADS) * 2 + k_lane_off);
                mma_f16(s1, qa[0][0], qa[0][1], qa[0][2], qa[0][3], k0, k1);
                mma_f16(s1, qa[1][0], qa[1][1], qa[1][2], qa[1][3], k2, k3);
            }

            uint32_t vb[8];
            {
                uint32_t addrA = vsb + (uint32_t)((16 * c + v_lane_row) * PADS + v_lane_col) * 2;
                ldm_x4t(vb[0], vb[1], vb[2], vb[3], addrA);
                ldm_x4t(vb[4], vb[5], vb[6], vb[7], addrA + 32);
            }

            uint32_t a0 = ex2_h2(cvt_f16x2(s0[1], s0[0]));
            uint32_t a1 = ex2_h2(cvt_f16x2(s0[3], s0[2]));
            uint32_t a2 = ex2_h2(cvt_f16x2(s1[1], s1[0]));
            uint32_t a3 = ex2_h2(cvt_f16x2(s1[3], s1[2]));

            lh0 = hadd2(lh0, a0);
            lh0 = hadd2(lh0, a2);
            lh1 = hadd2(lh1, a1);
            lh1 = hadd2(lh1, a3);

            #pragma unroll
            for (int dt = 0; dt < 4; dt++)
                mma_f16(o_[dt], a0, a1, a2, a3, vb[2 * dt], vb[2 * dt + 1]);
        }

        float2 f0 = unpack_h2(lh0);
        float2 f1 = unpack_h2(lh1);
        l0 += f0.x + f0.y;
        l1 += f1.x + f1.y;
    }

    l0 += __shfl_xor_sync(0xffffffffu, l0, 1);
    l0 += __shfl_xor_sync(0xffffffffu, l0, 2);
    l1 += __shfl_xor_sync(0xffffffffu, l1, 1);
    l1 += __shfl_xor_sync(0xffffffffu, l1, 2);
    const float inv0 = 1.0f / l0;
    const float inv1 = 1.0f / l1;

    const int r0 = q0 + wid * 16 + (lane >> 2);
    const int r1 = r0 + 8;
    const int cbase = h * 32 + 2 * (lane & 3);
    #pragma unroll
    for (int dt = 0; dt < 4; dt++) {
        int c = cbase + dt * 8;
        __nv_bfloat162 v0 = __floats2bfloat162_rn(o_[dt][0] * inv0, o_[dt][1] * inv0);
        __nv_bfloat162 v1 = __floats2bfloat162_rn(o_[dt][2] * inv1, o_[dt][3] * inv1);
        *(uint32_t*)&g_attnb[r0 * CCH + c] = *(uint32_t*)&v0;
        *(uint32_t*)&g_attnb[r1 * CCH + c] = *(uint32_t*)&v1;
    }
}

// ---------------------------------------------------------------------------
// O projection + residual, bf16 mma, 64(m) x 128(n) tiles -> 128 CTAs.
// (R8 measured-best shape: 3-stage cp.async, 8 warps = 2(m) x 4(n).)
// ---------------------------------------------------------------------------
__global__ void __launch_bounds__(256, 2) gemm_o_kernel(
    const float* __restrict__ x,
    const float* __restrict__ bo, const float* __restrict__ gamma,
    float* __restrict__ out)
{
    const __nv_bfloat16* W = g_Wb + 3 * CCH * CCH;

    __shared__ __nv_bfloat16 As[3][64 * 40];    // [m][k]
    __shared__ __nv_bfloat16 Bs[3][128 * 40];   // [n][k]

    const int tid  = threadIdx.x;
    const int lane = tid & 31;
    const int wid  = tid >> 5;
    const int wm   = wid & 1;
    const int wn   = wid >> 1;
    const int o0   = blockIdx.y * 64;
    const int n0   = blockIdx.x * 128;

    const int arow = tid >> 2, ac4 = tid & 3;

    auto issue = [&](int s, int b) {
        const char* wsrc = (const char*)W + (size_t)(o0 + arow) * CCH * 2 + s * 64 + ac4 * 16;
        cp16(sptr(&As[b][arow * 40]) + ac4 * 16, wsrc);
        const char* bsrc = (const char*)g_attnb + (size_t)(n0 + arow) * CCH * 2 + s * 64 + ac4 * 16;
        cp16(sptr(&Bs[b][arow * 40]) + ac4 * 16, bsrc);
        cp16(sptr(&Bs[b][(arow + 64) * 40]) + ac4 * 16, bsrc + (size_t)64 * CCH * 2);
        cp_commit();
    };
    issue(0, 0);
    issue(1, 1);

    float acc[2][4][4];
    #pragma unroll
    for (int i = 0; i < 2; i++)
        #pragma unroll
        for (int j = 0; j < 4; j++)
            #pragma unroll
            for (int r = 0; r < 4; r++) acc[i][j][r] = 0.0f;

    int cur = 0;
    for (int s = 0; s < 8; s++) {
        if (s == 7) cp_wait<0>(); else cp_wait<1>();
        __syncthreads();
        if (s + 2 < 8) {
            int nb = cur + 2; if (nb >= 3) nb -= 3;
            issue(s + 2, nb);
        }
        const uint32_t asb = sptr(As[cur]);
        const uint32_t bsb = sptr(Bs[cur]);
        cur++; if (cur == 3) cur = 0;

        uint32_t b[4][4];
        #pragma unroll
        for (int nt = 0; nt < 4; nt++) {
            uint32_t addr = bsb + (uint32_t)((wn * 32 + nt * 8 + (lane & 7)) * 40 + (lane >> 3) * 8) * 2;
            ldm_x4(b[nt][0], b[nt][1], b[nt][2], b[nt][3], addr);
        }
        #pragma unroll
        for (int ks = 0; ks < 2; ks++) {
            uint32_t a[2][4];
            #pragma unroll
            for (int mi = 0; mi < 2; mi++) {
                int row = wm * 32 + mi * 16 + (lane & 15);
                int col = (lane >> 4) * 8 + ks * 16;
                ldm_x4(a[mi][0], a[mi][1], a[mi][2], a[mi][3], asb + (uint32_t)(row * 40 + col) * 2);
            }
            #pragma unroll
            for (int mi = 0; mi < 2; mi++)
                #pragma unroll
                for (int nt = 0; nt < 4; nt++)
                    mma_bf16(acc[mi][nt], a[mi][0], a[mi][1], a[mi][2], a[mi][3],
                             b[nt][2 * ks], b[nt][2 * ks + 1]);
        }
    }

    const float g = gamma[0];
    float bz[2][2];
    #pragma unroll
    for (int mi = 0; mi < 2; mi++)
        #pragma unroll
        for (int hh = 0; hh < 2; hh++)
            bz[mi][hh] = bo[o0 + wm * 32 + mi * 16 + (lane >> 2) + 8 * hh];

    #pragma unroll
    for (int mi = 0; mi < 2; mi++)
        #pragma unroll
        for (int nt = 0; nt < 4; nt++) {
            int m = o0 + wm * 32 + mi * 16 + (lane >> 2);
            int n = n0 + wn * 32 + nt * 8 + 2 * (lane & 3);
            {
                float2 xv = *(const float2*)&x[m * NTOK + n];
                float2 ov;
                ov.x = xv.x + g * (acc[mi][nt][0] + bz[mi][0]);
                ov.y = xv.y + g * (acc[mi][nt][1] + bz[mi][0]);
                *(float2*)&out[m * NTOK + n] = ov;
            }
            {
                int m2 = m + 8;
                float2 xv = *(const float2*)&x[m2 * NTOK + n];
                float2 ov;
                ov.x = xv.x + g * (acc[mi][nt][2] + bz[mi][1]);
                ov.y = xv.y + g * (acc[mi][nt][3] + bz[mi][1]);
                *(float2*)&out[m2 * NTOK + n] = ov;
            }
        }
}

// ---------------------------------------------------------------------------
// Launch: inputs x, Wq, bq, Wk, bk, Wv, bv, Wo, bo, gamma
// ---------------------------------------------------------------------------
extern "C" void kernel_launch(void* const* d_in, const int* in_sizes, int n_in,
                              void* d_out, int out_size)
{
    const float* x     = (const float*)d_in[0];
    const float* Wq    = (const float*)d_in[1];
    const float* bq    = (const float*)d_in[2];
    const float* Wk    = (const float*)d_in[3];
    const float* bk    = (const float*)d_in[4];
    const float* Wv    = (const float*)d_in[5];
    const float* bv    = (const float*)d_in[6];
    const float* Wo    = (const float*)d_in[7];
    const float* bo    = (const float*)d_in[8];
    const float* gamma = (const float*)d_in[9];
    float* out = (float*)d_out;

    convert_kernel<<<320, 256>>>(x, Wq, Wk, Wv, Wo);

    dim3 qkvGrid(NTOK / 128, CCH / 64, 3);
    gemm_qkv_kernel<<<qkvGrid, 256>>>(bq, bk, bv);

    dim3 attnGrid(NTOK / TQ, NHEAD, 1);
    attn_mma_kernel<<<attnGrid, 256>>>();

    dim3 oGrid(NTOK / 128, CCH / 64, 1);
    gemm_o_kernel<<<oGrid, 256>>>(x, bo, gamma, out);
}